// round 8
// baseline (speedup 1.0000x reference)
#include <cuda_runtime.h>
#include <math.h>

#define NB 64      // batch
#define NT 1024    // seq len
#define ND 256     // input dim
#define NH 1024    // hidden
#define NC 1000    // classes
#define RCTAS 128  // persistent recurrence CTAs (1 CTA/SM resident)

typedef unsigned long long u64;

// ---------------- scratch (device globals) ----------------
// z buffer layout: [t][half][n][b32]  (half = batch 0..31 / 32..63)
// g_z[t] starts as xproj_t; recurrence red-accumulates W_hh*h_{t-1} into slice t.
// h = modrelu(z) computed on the fly by readers.
__device__ float g_z[NT * 2 * NH * 32];    // 256 MB
__device__ float g_xT[NT * ND * NB];       // [t][d][b]  (transposed x)
__device__ float g_wihT[ND * NH];          // [d][n]     (transposed w_ih)
__device__ unsigned g_arr[32];             // flags: [half][n-group]  (16 groups/half)

// ---------------- sync / math primitives ----------------
__device__ __forceinline__ unsigned ld_acq(const unsigned* p) {
    unsigned v;
    asm volatile("ld.global.acquire.gpu.u32 %0, [%1];" : "=r"(v) : "l"(p));
    return v;
}
__device__ __forceinline__ void red_release_add1(unsigned* p) {
    asm volatile("red.release.gpu.global.add.u32 [%0], 1;" :: "l"(p) : "memory");
}
#define FMA2(d, a, b) asm("fma.rn.f32x2 %0, %1, %2, %0;" : "+l"(d) : "l"(a), "l"(b))
__device__ __forceinline__ float lo32(u64 v) { return __uint_as_float((unsigned)v); }
__device__ __forceinline__ float hi32(u64 v) { return __uint_as_float((unsigned)(v >> 32)); }

__device__ __forceinline__ void red_add_v4(float* p, float v0, float v1, float v2, float v3) {
    asm volatile("red.global.add.v4.f32 [%0], {%1, %2, %3, %4};"
                 :: "l"(p), "f"(v0), "f"(v1), "f"(v2), "f"(v3) : "memory");
}
__device__ __forceinline__ float modrelu(float z, float bm) {
    float a = fabsf(z) + bm;
    return (a > 0.0f) ? copysignf(a, z) : 0.0f;
}
#define HBAR(id) asm volatile("bar.sync %0, 128;" :: "r"(id) : "memory")

// ---------------- init ----------------
__global__ void init_kernel() {
    if (threadIdx.x < 32) g_arr[threadIdx.x] = 0u;
}

// ---------------- transpose kernels (R7, unchanged) ----------------
__global__ __launch_bounds__(256) void xpose_kernel(const float* __restrict__ x) {
    __shared__ float T[64][65];
    const int t0 = blockIdx.x;
    const int d0 = blockIdx.y * 64;
    const int tid = threadIdx.x;
    const int b = tid & 63;
    #pragma unroll
    for (int it = 0; it < 4; it++) {
        int d4 = (tid >> 6) * 4 + it * 16;
        float4 v = __ldg((const float4*)(x + (long)b * (NT * ND) + (long)t0 * ND + d0 + d4));
        T[d4 + 0][b] = v.x; T[d4 + 1][b] = v.y;
        T[d4 + 2][b] = v.z; T[d4 + 3][b] = v.w;
    }
    __syncthreads();
    #pragma unroll
    for (int it = 0; it < 4; it++) {
        int dr = it * 16 + (tid >> 4);
        int b4 = (tid & 15) * 4;
        float4 v = make_float4(T[dr][b4], T[dr][b4 + 1], T[dr][b4 + 2], T[dr][b4 + 3]);
        *(float4*)(g_xT + ((long)t0 * ND + d0 + dr) * NB + b4) = v;
    }
}

__global__ __launch_bounds__(256) void wpose_kernel(const float* __restrict__ w_ih) {
    __shared__ float T[64][65];
    const int n0 = blockIdx.x * 64;
    const int d0 = blockIdx.y * 64;
    const int tid = threadIdx.x;
    const int n = tid & 63;
    #pragma unroll
    for (int it = 0; it < 4; it++) {
        int d4 = (tid >> 6) * 4 + it * 16;
        float4 v = __ldg((const float4*)(w_ih + (long)(n0 + n) * ND + d0 + d4));
        T[d4 + 0][n] = v.x; T[d4 + 1][n] = v.y;
        T[d4 + 2][n] = v.z; T[d4 + 3][n] = v.w;
    }
    __syncthreads();
    #pragma unroll
    for (int it = 0; it < 4; it++) {
        int dr = it * 16 + (tid >> 4);
        int n4 = (tid & 15) * 4;
        float4 v = make_float4(T[dr][n4], T[dr][n4 + 1], T[dr][n4 + 2], T[dr][n4 + 3]);
        *(float4*)(g_wihT + (long)(d0 + dr) * NH + n0 + n4) = v;
    }
}

// ---------------- kernel 1: xproj (FFMA2, R7-proven; store to [t][half][n][b32]) --------
__global__ __launch_bounds__(256) void xproj_kernel() {
    __shared__ float As_dup[64 * 128];   // [k][2b dup]  32 KB
    __shared__ float Bs[64 * 64];        // [k][n]       16 KB

    const int t0 = blockIdx.x;
    const int n0 = blockIdx.y * 64;
    const int tid = threadIdx.x;
    const int tx = tid & 15, ty = tid >> 4;

    u64 acc[4][2];
    #pragma unroll
    for (int i = 0; i < 4; i++) { acc[i][0] = 0ull; acc[i][1] = 0ull; }

    for (int p = 0; p < 4; p++) {
        __syncthreads();
        {
            const float2* xsrc = (const float2*)(g_xT + ((long)t0 * ND + p * 64) * NB);
            float4* Ad4 = (float4*)As_dup;
            #pragma unroll
            for (int it = 0; it < 8; it++) {
                int f2 = it * 256 + tid;
                float2 v = __ldg(&xsrc[f2]);
                Ad4[f2] = make_float4(v.x, v.x, v.y, v.y);
            }
        }
        {
            const float4* wsrc = (const float4*)(g_wihT + (long)(p * 64) * NH + n0);
            #pragma unroll
            for (int it = 0; it < 4; it++) {
                int f4 = it * 256 + tid;
                int k = f4 >> 4, n4 = f4 & 15;
                ((float4*)Bs)[f4] = __ldg(&wsrc[(long)k * (NH / 4) + n4]);
            }
        }
        __syncthreads();

        #pragma unroll 8
        for (int kk = 0; kk < 64; kk++) {
            const ulonglong2 bp  = *(const ulonglong2*)(Bs + kk * 64 + tx * 4);
            const ulonglong2 a01 = *(const ulonglong2*)(As_dup + kk * 128 + ty * 8);
            const ulonglong2 a23 = *(const ulonglong2*)(As_dup + kk * 128 + ty * 8 + 4);
            FMA2(acc[0][0], a01.x, bp.x); FMA2(acc[0][1], a01.x, bp.y);
            FMA2(acc[1][0], a01.y, bp.x); FMA2(acc[1][1], a01.y, bp.y);
            FMA2(acc[2][0], a23.x, bp.x); FMA2(acc[2][1], a23.x, bp.y);
            FMA2(acc[3][0], a23.y, bp.x); FMA2(acc[3][1], a23.y, bp.y);
        }
    }

    // store: z[t0][half][n0+tx*4+j][(ty&7)*4]  where half = ty>>3
    const int ph = ty >> 3;
    const int boff = (ty & 7) * 4;
    #pragma unroll
    for (int j = 0; j < 4; j++) {
        int jp = j >> 1;
        float4 v;
        if (j & 1) v = make_float4(hi32(acc[0][jp]), hi32(acc[1][jp]),
                                   hi32(acc[2][jp]), hi32(acc[3][jp]));
        else       v = make_float4(lo32(acc[0][jp]), lo32(acc[1][jp]),
                                   lo32(acc[2][jp]), lo32(acc[3][jp]));
        *(float4*)(g_z + (((long)t0 * 2 + ph) * NH + n0 + tx * 4 + j) * 32 + boff) = v;
    }
}

// ---------------- kernel 2: persistent recurrence, two warp-specialized half-chains ----
// CTA (nc = cta&15, kc = cta>>4). Warps 0-3 = batch half 0, warps 4-7 = half 1.
// Shared read-only Bs = W_hh slice. Per half per step:
//   wait flags[p][2kc],[2kc+1] >= 8(t-1)  ->  stage h chunk (dup)  ->  FFMA2 GEMM
//   ->  red.v4 into z[t][p]  ->  named-bar  ->  one release-arrival on flags[p][nc].
__global__ __launch_bounds__(256) void recur_kernel(
    const float* __restrict__ w_hh, const float* __restrict__ b_mod)
{
    extern __shared__ float sm[];
    float* Bs  = sm;                    // [128][64]  32 KB (shared W, one-time)
    float* As0 = sm + 128 * 64;         // half0: [128][64] dup  32 KB
    float* As1 = sm + 2 * 128 * 64;     // half1

    const int tid = threadIdx.x;
    const int cta = blockIdx.x;
    const int nc = cta & 15;
    const int kc = cta >> 4;

    // ---- one-time: W_hh slice transposed into shared smem (all 256 threads) ----
    #pragma unroll
    for (int it = 0; it < 8; it++) {
        int f4 = it * 256 + tid;
        int np = f4 >> 5, k0 = (f4 & 31) * 4;
        float4 w = __ldg((const float4*)(w_hh + (long)(nc * 64 + np) * NH + kc * 128 + k0));
        Bs[(k0 + 0) * 64 + np] = w.x;
        Bs[(k0 + 1) * 64 + np] = w.y;
        Bs[(k0 + 2) * 64 + np] = w.z;
        Bs[(k0 + 3) * 64 + np] = w.w;
    }
    __syncthreads();

    // ---- per-half identities ----
    const int p = tid >> 7;              // batch half
    const int htid = tid & 127;
    const int tx = htid & 15, ty = htid >> 4;    // ty 0..7 (b-quads), tx 0..15 (n-quads)
    float* As = p ? As1 : As0;
    const int barid = 1 + p;
    unsigned* flag0 = &g_arr[p * 16 + 2 * kc];
    unsigned* flag1 = &g_arr[p * 16 + 2 * kc + 1];
    unsigned* myarr = &g_arr[p * 16 + nc];

    for (int t = 1; t < NT; t++) {
        // ---- wait: chunk kc of z_{t-1}[p] complete (8 producers per group) ----
        if (t > 1) {
            unsigned target = (unsigned)(8 * (t - 1));
            if (htid == 0)  while (ld_acq(flag0) < target) { __nanosleep(16); }
            if (htid == 33) while (ld_acq(flag1) < target) { __nanosleep(16); }
        }
        HBAR(barid);

        // ---- stage: As[k][2b,2b+1] = modrelu(z_{t-1}[p][kc*128+k][b]) dup ----
        {
            const float2* zsrc = (const float2*)(g_z +
                                 (((long)(t - 1) * 2 + p) * NH + kc * 128) * 32);
            float4* Ad4 = (float4*)As;
            #pragma unroll
            for (int it = 0; it < 16; it++) {
                int f2 = it * 128 + htid;            // 2048 f2 = 128k x 16
                int n = kc * 128 + (f2 >> 4);
                float2 z = __ldcg(&zsrc[f2]);
                float bm = __ldg(&b_mod[n]);
                float hx = modrelu(z.x, bm);
                float hy = modrelu(z.y, bm);
                Ad4[f2] = make_float4(hx, hx, hy, hy);
            }
        }
        HBAR(barid);

        // ---- GEMM: 128 kk x (3 LDS.128 + 8 FFMA2), tile 64n x 32b ----
        u64 acc[4][2];
        #pragma unroll
        for (int i = 0; i < 4; i++) { acc[i][0] = 0ull; acc[i][1] = 0ull; }

        #pragma unroll 8
        for (int kk = 0; kk < 128; kk++) {
            const ulonglong2 bp  = *(const ulonglong2*)(Bs + kk * 64 + tx * 4);
            const ulonglong2 a01 = *(const ulonglong2*)(As + kk * 64 + ty * 8);
            const ulonglong2 a23 = *(const ulonglong2*)(As + kk * 64 + ty * 8 + 4);
            FMA2(acc[0][0], a01.x, bp.x); FMA2(acc[0][1], a01.x, bp.y);
            FMA2(acc[1][0], a01.y, bp.x); FMA2(acc[1][1], a01.y, bp.y);
            FMA2(acc[2][0], a23.x, bp.x); FMA2(acc[2][1], a23.x, bp.y);
            FMA2(acc[3][0], a23.y, bp.x); FMA2(acc[3][1], a23.y, bp.y);
        }

        // ---- red-accumulate partials into z_t[p] ----
        {
            float* zdst = g_z + (((long)t * 2 + p) * NH + nc * 64) * 32;
            #pragma unroll
            for (int j = 0; j < 4; j++) {
                int jp = j >> 1;
                float v0, v1, v2, v3;
                if (j & 1) { v0 = hi32(acc[0][jp]); v1 = hi32(acc[1][jp]);
                             v2 = hi32(acc[2][jp]); v3 = hi32(acc[3][jp]); }
                else       { v0 = lo32(acc[0][jp]); v1 = lo32(acc[1][jp]);
                             v2 = lo32(acc[2][jp]); v3 = lo32(acc[3][jp]); }
                red_add_v4(zdst + (long)(tx * 4 + j) * 32 + ty * 4, v0, v1, v2, v3);
            }
        }

        // ---- arrive: named-bar (exec+cta-mem sync), then one gpu-release arrival ----
        HBAR(barid);
        if (htid == 0) red_release_add1(myarr);
    }
}

// ---------------- kernel 3: fc head out[b][c] = modrelu(z_last)[:,b] . w_fc[c][:] + b_fc[c]
__global__ __launch_bounds__(256) void fc_kernel(
    const float* __restrict__ w_fc, const float* __restrict__ b_fc,
    const float* __restrict__ b_mod, float* __restrict__ out)
{
    __shared__ float As[64][64];   // [k][b] = h_last slab
    __shared__ float Bs[64][64];   // [k][c']
    const int n0 = blockIdx.x * 64;
    const int tid = threadIdx.x;
    const int tx = tid & 15, ty = tid >> 4;
    float acc[4][4] = {};

    for (int s = 0; s < 16; s++) {
        __syncthreads();
        #pragma unroll
        for (int it = 0; it < 4; it++) {
            int f4 = it * 256 + tid;
            int k = f4 >> 4, r = f4 & 15;
            int ph = r >> 3, b4 = (r & 7) * 4;
            int n = s * 64 + k;
            float4 z = __ldcg((const float4*)(g_z +
                        (((long)(NT - 1) * 2 + ph) * NH + n) * 32 + b4));
            float bm = __ldg(&b_mod[n]);
            float4 h;
            h.x = modrelu(z.x, bm); h.y = modrelu(z.y, bm);
            h.z = modrelu(z.z, bm); h.w = modrelu(z.w, bm);
            ((float4*)As)[f4] = h;
        }
        #pragma unroll
        for (int it = 0; it < 4; it++) {
            int f4 = it * 256 + tid;
            int np = f4 >> 4, k0 = (f4 & 15) * 4;
            int row = n0 + np; if (row >= NC) row = NC - 1;
            float4 w = *(const float4*)(w_fc + (long)row * NH + s * 64 + k0);
            Bs[k0 + 0][np] = w.x; Bs[k0 + 1][np] = w.y;
            Bs[k0 + 2][np] = w.z; Bs[k0 + 3][np] = w.w;
        }
        __syncthreads();
        #pragma unroll 8
        for (int kk = 0; kk < 64; kk++) {
            float4 av = *(const float4*)(&As[kk][ty * 4]);
            float4 bv = *(const float4*)(&Bs[kk][tx * 4]);
            float a[4] = {av.x, av.y, av.z, av.w};
            float b[4] = {bv.x, bv.y, bv.z, bv.w};
            #pragma unroll
            for (int i = 0; i < 4; i++)
                #pragma unroll
                for (int j = 0; j < 4; j++)
                    acc[i][j] += a[i] * b[j];
        }
    }
    #pragma unroll
    for (int i = 0; i < 4; i++) {
        #pragma unroll
        for (int j = 0; j < 4; j++) {
            int c = n0 + tx * 4 + j;
            if (c < NC) out[(long)(ty * 4 + i) * NC + c] = acc[i][j] + __ldg(&b_fc[c]);
        }
    }
}

// ---------------- launch ----------------
extern "C" void kernel_launch(void* const* d_in, const int* in_sizes, int n_in,
                              void* d_out, int out_size)
{
    const float* x     = (const float*)d_in[0];  // [64,1024,256]
    const float* w_ih  = (const float*)d_in[1];  // [1024,256]
    const float* w_hh  = (const float*)d_in[2];  // [1024,1024]
    const float* b_mod = (const float*)d_in[3];  // [1024]
    const float* w_fc  = (const float*)d_in[4];  // [1000,1024]
    const float* b_fc  = (const float*)d_in[5];  // [1000]
    float* out = (float*)d_out;                  // [64,1000]

    cudaFuncSetAttribute(recur_kernel, cudaFuncAttributeMaxDynamicSharedMemorySize, 98304);

    init_kernel<<<1, 32>>>();
    xpose_kernel<<<dim3(NT, ND / 64), 256>>>(x);
    wpose_kernel<<<dim3(NH / 64, ND / 64), 256>>>(w_ih);
    xproj_kernel<<<dim3(NT, NH / 64), 256>>>();
    recur_kernel<<<RCTAS, 256, 98304>>>(w_hh, b_mod);
    fc_kernel<<<(NC + 63) / 64, 256>>>(w_fc, b_fc, b_mod, out);
}